// round 3
// baseline (speedup 1.0000x reference)
#include <cuda_runtime.h>
#include <cstdint>

#define INW    128
#define OUTW   128
#define BATCHN 128

// One fused kernel: grid = 128 (one block per output o), block = 1024
//   = 8 i-slices x 128 batches  (8 warps per SMSP for latency hiding)
__global__ void __launch_bounds__(1024, 1) fused_kernel(
    const float* __restrict__ x,
    const float* __restrict__ weight,
    const float* __restrict__ bias,
    const float* __restrict__ means,
    const int*   __restrict__ mask,
    float*       __restrict__ out)
{
    __shared__ float         sW[INW * 33];      // [i]: 16 (level0) + 16 (level1), row pad 33
    __shared__ unsigned char sSB[INW * 132];    // [i][b] byte = s0 | s1<<4, row pad 132
    __shared__ int4          sIdx[INW];         // 4 taps per table
    __shared__ float         red[1024];

    const int tid = threadIdx.x;
    const int o   = blockIdx.x;

    const float a0 = fabsf(means[0]);
    const float a1 = fabsf(means[1]);

    // ---------------- sign bytes: 4096 words, 4 per thread ----------------
    #pragma unroll
    for (int j = 0; j < 4; j++) {
        int wlin = j * 1024 + tid;           // [0, 4096)
        int i    = wlin & 127;               // input index (lanes -> consecutive i: coalesced LDG)
        int b0   = (wlin >> 7) * 4;          // batch group of 4
        unsigned pack = 0;
        #pragma unroll
        for (int k = 0; k < 4; k++) {
            float v   = x[(b0 + k) * INW + i];
            bool  s0  = (v >= 0.0f);
            float thr = s0 ? a0 : -a0;
            bool  s1  = (v >= thr);
            unsigned byte = (s0 ? 1u : 0u) | (s1 ? 16u : 0u);
            pack |= byte << (k * 8);
        }
        *(unsigned*)&sSB[i * 132 + b0] = pack;   // bank = i%32 : conflict-free
    }

    // ---------------- collapsed LUT via WHT: one (table, level) per thread ----------------
    // W[l][g] = (1/16) * WHT( WHT(w) .* a_l^{popc(S)} )   (XOR-convolution diagonalization)
    if (tid < 256) {
        const int t = tid & 127;
        const int l = tid >> 7;
        float f[16];
        const float4* wp = (const float4*)(weight + (size_t)(o * INW + t) * 16);
        #pragma unroll
        for (int q = 0; q < 4; q++) {
            float4 v = wp[q];
            f[q*4+0] = v.x; f[q*4+1] = v.y; f[q*4+2] = v.z; f[q*4+3] = v.w;
        }
        // forward WHT
        #pragma unroll
        for (int s = 1; s < 16; s <<= 1)
            #pragma unroll
            for (int i2 = 0; i2 < 16; i2++)
                if (!(i2 & s)) { float u = f[i2], v = f[i2 ^ s]; f[i2] = u + v; f[i2 ^ s] = u - v; }

        const float a = (l == 0) ? a0 : a1;
        float pw[5];
        pw[0] = 1.0f / 16.0f;
        pw[1] = pw[0] * a; pw[2] = pw[1] * a; pw[3] = pw[2] * a; pw[4] = pw[3] * a;
        #pragma unroll
        for (int i2 = 0; i2 < 16; i2++) f[i2] *= pw[__popc(i2)];
        // inverse WHT (same butterfly)
        #pragma unroll
        for (int s = 1; s < 16; s <<= 1)
            #pragma unroll
            for (int i2 = 0; i2 < 16; i2++)
                if (!(i2 & s)) { float u = f[i2], v = f[i2 ^ s]; f[i2] = u + v; f[i2 ^ s] = u - v; }

        float* dst = &sW[t * 33 + l * 16];
        #pragma unroll
        for (int i2 = 0; i2 < 16; i2++) dst[i2] = f[i2];
    } else if (tid < 384) {
        sIdx[tid - 256] = ((const int4*)mask)[o * INW + (tid - 256)];
    }
    __syncthreads();

    // ---------------- main gather + accumulate: 16 tables per thread ----------------
    const int b = tid & 127;     // batch (consecutive across warp lanes)
    const int s = tid >> 7;      // i-slice 0..7
    const unsigned char* sbB = &sSB[b];
    const float* sWs = &sW[s * 16 * 33];

    float acc0 = 0.0f, acc1 = 0.0f;
    #pragma unroll
    for (int k = 0; k < 16; k++) {
        const int4 id = sIdx[s * 16 + k];        // uniform per warp: broadcast LDS
        unsigned v0 = sbB[id.x * 132];           // bytes hold s0|s1<<4
        unsigned v1 = sbB[id.y * 132];
        unsigned v2 = sbB[id.z * 132];
        unsigned v3 = sbB[id.w * 132];
        unsigned vc = (v0 + v1 * 2u) + (v2 + v3 * 2u) * 4u;  // g0 in bits 0-3, g1 in bits 4-7
        unsigned g0 = vc & 15u;
        unsigned g1 = vc >> 4;
        acc0 += sWs[k * 33 + g0];
        acc1 += sWs[k * 33 + 16 + g1];
    }

    red[tid] = acc0 + acc1;
    __syncthreads();
    if (tid < 128) {
        float tot = bias[o];
        #pragma unroll
        for (int ss = 0; ss < 8; ss++) tot += red[tid + 128 * ss];
        out[tid * OUTW + o] = tot;
    }
}

// ---------------------------------------------------------------------------
extern "C" void kernel_launch(void* const* d_in, const int* in_sizes, int n_in,
                              void* d_out, int out_size) {
    const float* x      = (const float*)d_in[0];
    const float* weight = (const float*)d_in[1];
    const float* bias   = (const float*)d_in[2];
    const float* means  = (const float*)d_in[3];
    const int*   mask   = (const int*)  d_in[4];
    float* out = (float*)d_out;

    fused_kernel<<<OUTW, 1024>>>(x, weight, bias, means, mask, out);
}

// round 4
// speedup vs baseline: 1.1834x; 1.1834x over previous
#include <cuda_runtime.h>
#include <cstdint>

#define INW    128
#define OUTW   128
#define BATCHN 128

// grid = 128 (one block per output o), block = 512 = 16 warps.
// Each warp handles 8 i-rows x ALL 128 batches (4 batches per lane via SWAR bytes).
// Table lookups via register-resident table + warp shuffle (conflict-free).
__global__ void __launch_bounds__(512, 1) fused_kernel(
    const float* __restrict__ x,
    const float* __restrict__ weight,
    const float* __restrict__ bias,
    const float* __restrict__ means,
    const int*   __restrict__ mask,
    float*       __restrict__ out)
{
    __shared__ float         sW[INW * 33];      // [i]: 32 entries (16 per level), row pad 33
    __shared__ unsigned char sSB[INW * 132];    // [i][b] byte = s0 | s1<<4, row pad 132
    __shared__ int4          sIdx[INW];         // 4 taps per table
    __shared__ float         red[16 * BATCHN];  // per-warp partials [w][b]

    const int tid  = threadIdx.x;
    const int lane = tid & 31;
    const int w    = tid >> 5;       // warp 0..15
    const int o    = blockIdx.x;

    const float a0 = fabsf(means[0]);
    const float a1 = fabsf(means[1]);

    // ---------------- sign bytes: 4096 words, 8 per thread ----------------
    #pragma unroll
    for (int j = 0; j < 8; j++) {
        int wlin = j * 512 + tid;            // [0, 4096)
        int i    = wlin & 127;               // input index (lanes -> consecutive i: coalesced LDG)
        int b0   = (wlin >> 7) * 4;          // batch group of 4
        unsigned pack = 0;
        #pragma unroll
        for (int k = 0; k < 4; k++) {
            float v   = x[(b0 + k) * INW + i];
            bool  s0  = (v >= 0.0f);
            float thr = s0 ? a0 : -a0;
            bool  s1  = (v >= thr);
            unsigned byte = (s0 ? 1u : 0u) | (s1 ? 16u : 0u);
            pack |= byte << (k * 8);
        }
        *(unsigned*)&sSB[i * 132 + b0] = pack;   // bank = i%32 : conflict-free
    }

    // ---------------- collapsed LUT via WHT: one (table, level) per thread ----------------
    // W[l][g] = (1/16) * WHT( WHT(w) .* a_l^{popc(S)} )
    if (tid < 256) {
        const int t = tid & 127;
        const int l = tid >> 7;
        float f[16];
        const float4* wp = (const float4*)(weight + (size_t)(o * INW + t) * 16);
        #pragma unroll
        for (int q = 0; q < 4; q++) {
            float4 v = wp[q];
            f[q*4+0] = v.x; f[q*4+1] = v.y; f[q*4+2] = v.z; f[q*4+3] = v.w;
        }
        #pragma unroll
        for (int s = 1; s < 16; s <<= 1)
            #pragma unroll
            for (int i2 = 0; i2 < 16; i2++)
                if (!(i2 & s)) { float u = f[i2], v = f[i2 ^ s]; f[i2] = u + v; f[i2 ^ s] = u - v; }

        const float a = (l == 0) ? a0 : a1;
        float pw[5];
        pw[0] = 1.0f / 16.0f;
        pw[1] = pw[0] * a; pw[2] = pw[1] * a; pw[3] = pw[2] * a; pw[4] = pw[3] * a;
        #pragma unroll
        for (int i2 = 0; i2 < 16; i2++) f[i2] *= pw[__popc(i2)];
        #pragma unroll
        for (int s = 1; s < 16; s <<= 1)
            #pragma unroll
            for (int i2 = 0; i2 < 16; i2++)
                if (!(i2 & s)) { float u = f[i2], v = f[i2 ^ s]; f[i2] = u + v; f[i2 ^ s] = u - v; }

        float* dst = &sW[t * 33 + l * 16];
        #pragma unroll
        for (int i2 = 0; i2 < 16; i2++) dst[i2] = f[i2];
    } else if (tid < 384) {
        sIdx[tid - 256] = ((const int4*)mask)[o * INW + (tid - 256)];
    }
    __syncthreads();

    // ---------------- main loop: warp w -> i in [w*8, w*8+8), lane -> batches 4*lane..+3 ----
    float acc0 = 0.0f, acc1 = 0.0f, acc2 = 0.0f, acc3 = 0.0f;
    const unsigned boff = lane * 4u;

    #pragma unroll
    for (int k = 0; k < 8; k++) {
        const int i = w * 8 + k;
        const int4 id = sIdx[i];                         // uniform: broadcast LDS.128
        const float tbl = sW[i * 33 + lane];             // bank (i+lane)%32: conflict-free

        unsigned v0 = *(const unsigned*)&sSB[id.x * 132 + boff];  // banks = lane: conflict-free
        unsigned v1 = *(const unsigned*)&sSB[id.y * 132 + boff];
        unsigned v2 = *(const unsigned*)&sSB[id.z * 132 + boff];
        unsigned v3 = *(const unsigned*)&sSB[id.w * 132 + boff];

        // byte m of VC = (g0 | g1<<4) for batch 4*lane+m
        unsigned VC = (v0 & 0x11111111u)
                    + ((v1 & 0x11111111u) << 1)
                    + ((v2 & 0x11111111u) << 2)
                    + ((v3 & 0x11111111u) << 3);

        unsigned c0 = VC & 0xffu;
        unsigned c1 = (VC >> 8) & 0xffu;
        unsigned c2 = (VC >> 16) & 0xffu;
        unsigned c3 = VC >> 24;

        acc0 += __shfl_sync(0xffffffffu, tbl, c0 & 15u)
              + __shfl_sync(0xffffffffu, tbl, (c0 >> 4) + 16u);
        acc1 += __shfl_sync(0xffffffffu, tbl, c1 & 15u)
              + __shfl_sync(0xffffffffu, tbl, (c1 >> 4) + 16u);
        acc2 += __shfl_sync(0xffffffffu, tbl, c2 & 15u)
              + __shfl_sync(0xffffffffu, tbl, (c2 >> 4) + 16u);
        acc3 += __shfl_sync(0xffffffffu, tbl, c3 & 15u)
              + __shfl_sync(0xffffffffu, tbl, (c3 >> 4) + 16u);
    }

    // partials: red[w][b]
    ((float4*)red)[w * 32 + lane] = make_float4(acc0, acc1, acc2, acc3);
    __syncthreads();

    // ---------------- final reduce over 16 warps, add bias, store ----------------
    if (tid < 128) {
        const int b = tid;
        float tot = bias[o];
        #pragma unroll
        for (int ww = 0; ww < 16; ww++) tot += red[ww * BATCHN + b];  // bank b%32: conflict-free
        out[b * OUTW + o] = tot;
    }
}

// ---------------------------------------------------------------------------
extern "C" void kernel_launch(void* const* d_in, const int* in_sizes, int n_in,
                              void* d_out, int out_size) {
    const float* x      = (const float*)d_in[0];
    const float* weight = (const float*)d_in[1];
    const float* bias   = (const float*)d_in[2];
    const float* means  = (const float*)d_in[3];
    const int*   mask   = (const int*)  d_in[4];
    float* out = (float*)d_out;

    fused_kernel<<<OUTW, 512>>>(x, weight, bias, means, mask, out);
}

// round 5
// speedup vs baseline: 1.2258x; 1.0358x over previous
#include <cuda_runtime.h>
#include <cstdint>

#define INW    128
#define OUTW   128
#define BATCHN 128

// grid = 128 (one block per output o), block = 1024 = 32 warps.
// Warp w handles i in [w*4, w*4+4), lane handles 4 batches (SWAR bytes).
// Table lookups: register-resident 32-entry table + warp shuffle (conflict-free).
__global__ void __launch_bounds__(1024, 1) fused_kernel(
    const float* __restrict__ x,
    const float* __restrict__ weight,
    const float* __restrict__ bias,
    const float* __restrict__ means,
    const int*   __restrict__ mask,
    float*       __restrict__ out)
{
    __shared__ float         sW[INW * 33];      // [i]: 16 (lvl0) + 16 (lvl1), row pad 33
    __shared__ unsigned char sSB[INW * 132];    // [i][b] byte = s0 | s1<<4, row pad 132
    __shared__ int4          sIdx[INW];         // 4 taps per table
    __shared__ float         red[32 * BATCHN];  // per-warp partials [w][b]

    const int tid  = threadIdx.x;
    const int lane = tid & 31;
    const int w    = tid >> 5;       // warp 0..31
    const int o    = blockIdx.x;

    const float a0 = fabsf(means[0]);
    const float a1 = fabsf(means[1]);

    // ---------------- sign bytes: 4096 words, 4 per thread ----------------
    #pragma unroll
    for (int j = 0; j < 4; j++) {
        int wlin = j * 1024 + tid;           // [0, 4096)
        int i    = wlin & 127;               // input index (lanes -> consecutive i: coalesced)
        int b0   = (wlin >> 7) * 4;          // batch group of 4
        unsigned pack = 0;
        #pragma unroll
        for (int k = 0; k < 4; k++) {
            float v   = x[(b0 + k) * INW + i];
            bool  s0  = (v >= 0.0f);
            float thr = s0 ? a0 : -a0;
            bool  s1  = (v >= thr);
            unsigned byte = (s0 ? 1u : 0u) | (s1 ? 16u : 0u);
            pack |= byte << (k * 8);
        }
        *(unsigned*)&sSB[i * 132 + b0] = pack;   // bank = i%32 : conflict-free
    }

    // ---------------- collapsed LUT via WHT: one (table, level) per thread ----------------
    // W[l][g] = (1/16) * WHT( WHT(w) .* a_l^{popc(S)} )
    if (tid < 256) {
        const int t = tid & 127;
        const int l = tid >> 7;
        float f[16];
        const float4* wp = (const float4*)(weight + (size_t)(o * INW + t) * 16);
        #pragma unroll
        for (int q = 0; q < 4; q++) {
            float4 v = wp[q];
            f[q*4+0] = v.x; f[q*4+1] = v.y; f[q*4+2] = v.z; f[q*4+3] = v.w;
        }
        #pragma unroll
        for (int s = 1; s < 16; s <<= 1)
            #pragma unroll
            for (int i2 = 0; i2 < 16; i2++)
                if (!(i2 & s)) { float u = f[i2], v = f[i2 ^ s]; f[i2] = u + v; f[i2 ^ s] = u - v; }

        const float a = (l == 0) ? a0 : a1;
        float pw[5];
        pw[0] = 1.0f / 16.0f;
        pw[1] = pw[0] * a; pw[2] = pw[1] * a; pw[3] = pw[2] * a; pw[4] = pw[3] * a;
        #pragma unroll
        for (int i2 = 0; i2 < 16; i2++) f[i2] *= pw[__popc(i2)];
        #pragma unroll
        for (int s = 1; s < 16; s <<= 1)
            #pragma unroll
            for (int i2 = 0; i2 < 16; i2++)
                if (!(i2 & s)) { float u = f[i2], v = f[i2 ^ s]; f[i2] = u + v; f[i2 ^ s] = u - v; }

        float* dst = &sW[t * 33 + l * 16];
        #pragma unroll
        for (int i2 = 0; i2 < 16; i2++) dst[i2] = f[i2];
    } else if (tid < 384) {
        sIdx[tid - 256] = ((const int4*)mask)[o * INW + (tid - 256)];
    }
    __syncthreads();

    // ---------------- main loop: warp w -> 4 i-rows, lane -> batches 4*lane..+3 ----------
    float acc0 = 0.0f, acc1 = 0.0f, acc2 = 0.0f, acc3 = 0.0f;
    const unsigned boff = lane * 4u;

    #pragma unroll
    for (int k = 0; k < 4; k++) {
        const int i = w * 4 + k;
        const int4 id = sIdx[i];                         // uniform: broadcast LDS.128
        const float tbl = sW[i * 33 + lane];             // bank (i+lane)%32: conflict-free

        unsigned v0 = *(const unsigned*)&sSB[id.x * 132 + boff];  // banks = lane: conflict-free
        unsigned v1 = *(const unsigned*)&sSB[id.y * 132 + boff];
        unsigned v2 = *(const unsigned*)&sSB[id.z * 132 + boff];
        unsigned v3 = *(const unsigned*)&sSB[id.w * 132 + boff];

        // byte m of VC = (g0 | g1<<4) for batch 4*lane+m
        unsigned VC = (v0 & 0x11111111u)
                    + ((v1 & 0x11111111u) << 1)
                    + ((v2 & 0x11111111u) << 2)
                    + ((v3 & 0x11111111u) << 3);

        unsigned c0 = VC & 0xffu;
        unsigned c1 = (VC >> 8) & 0xffu;
        unsigned c2 = (VC >> 16) & 0xffu;
        unsigned c3 = VC >> 24;

        acc0 += __shfl_sync(0xffffffffu, tbl, c0 & 15u)
              + __shfl_sync(0xffffffffu, tbl, (c0 >> 4) + 16u);
        acc1 += __shfl_sync(0xffffffffu, tbl, c1 & 15u)
              + __shfl_sync(0xffffffffu, tbl, (c1 >> 4) + 16u);
        acc2 += __shfl_sync(0xffffffffu, tbl, c2 & 15u)
              + __shfl_sync(0xffffffffu, tbl, (c2 >> 4) + 16u);
        acc3 += __shfl_sync(0xffffffffu, tbl, c3 & 15u)
              + __shfl_sync(0xffffffffu, tbl, (c3 >> 4) + 16u);
    }

    // partials: red[w][b]
    ((float4*)red)[w * 32 + lane] = make_float4(acc0, acc1, acc2, acc3);
    __syncthreads();

    // ---------------- final reduce over 32 warps, add bias, store ----------------
    if (tid < 128) {
        const int b = tid;
        float tot = bias[o];
        #pragma unroll
        for (int ww = 0; ww < 32; ww++) tot += red[ww * BATCHN + b];  // bank b%32: conflict-free
        out[b * OUTW + o] = tot;
    }
}

// ---------------------------------------------------------------------------
extern "C" void kernel_launch(void* const* d_in, const int* in_sizes, int n_in,
                              void* d_out, int out_size) {
    const float* x      = (const float*)d_in[0];
    const float* weight = (const float*)d_in[1];
    const float* bias   = (const float*)d_in[2];
    const float* means  = (const float*)d_in[3];
    const int*   mask   = (const int*)  d_in[4];
    float* out = (float*)d_out;

    fused_kernel<<<OUTW, 1024>>>(x, weight, bias, means, mask, out);
}

// round 6
// speedup vs baseline: 1.2620x; 1.0295x over previous
#include <cuda_runtime.h>
#include <cstdint>

#define INW    128
#define OUTW   128
#define BATCHN 128

// grid = 128 (one block per output o), block = 512 = 16 warps.
// WARP-SPECIALIZED PROLOGUE:
//   warps 0-7  : collapsed LUT build via WHT (FMA-chain bound)
//   warps 8-15 : sign-byte table + index load (LDG-latency bound)
// then one barrier and the SWAR+shuffle main loop on all 16 warps.
__global__ void __launch_bounds__(512, 1) fused_kernel(
    const float* __restrict__ x,
    const float* __restrict__ weight,
    const float* __restrict__ bias,
    const float* __restrict__ means,
    const int*   __restrict__ mask,
    float*       __restrict__ out)
{
    __shared__ float         sW[INW * 33];      // [i]: 16 (lvl0) + 16 (lvl1), row pad 33
    __shared__ unsigned char sSB[INW * 132];    // [i][b] byte = s0 | s1<<4, row pad 132
    __shared__ int4          sIdx[INW];         // 4 taps per table
    __shared__ float         red[16 * BATCHN];  // per-warp partials [w][b]

    const int tid  = threadIdx.x;
    const int lane = tid & 31;
    const int w    = tid >> 5;       // warp 0..15
    const int o    = blockIdx.x;

    const float a0 = fabsf(means[0]);
    const float a1 = fabsf(means[1]);

    if (tid < 256) {
        // ======== warps 0-7: collapsed LUT via WHT, one (table, level) per thread ========
        // W[l][g] = (1/16) * WHT( WHT(w) .* a_l^{popc(S)} )
        const int t = tid & 127;
        const int l = tid >> 7;
        float f[16];
        const float4* wp = (const float4*)(weight + (size_t)(o * INW + t) * 16);
        #pragma unroll
        for (int q = 0; q < 4; q++) {
            float4 v = wp[q];
            f[q*4+0] = v.x; f[q*4+1] = v.y; f[q*4+2] = v.z; f[q*4+3] = v.w;
        }
        #pragma unroll
        for (int s = 1; s < 16; s <<= 1)
            #pragma unroll
            for (int i2 = 0; i2 < 16; i2++)
                if (!(i2 & s)) { float u = f[i2], v = f[i2 ^ s]; f[i2] = u + v; f[i2 ^ s] = u - v; }

        const float a = (l == 0) ? a0 : a1;
        float pw[5];
        pw[0] = 1.0f / 16.0f;
        pw[1] = pw[0] * a; pw[2] = pw[1] * a; pw[3] = pw[2] * a; pw[4] = pw[3] * a;
        #pragma unroll
        for (int i2 = 0; i2 < 16; i2++) f[i2] *= pw[__popc(i2)];
        #pragma unroll
        for (int s = 1; s < 16; s <<= 1)
            #pragma unroll
            for (int i2 = 0; i2 < 16; i2++)
                if (!(i2 & s)) { float u = f[i2], v = f[i2 ^ s]; f[i2] = u + v; f[i2 ^ s] = u - v; }

        float* dst = &sW[t * 33 + l * 16];
        #pragma unroll
        for (int i2 = 0; i2 < 16; i2++) dst[i2] = f[i2];
    } else {
        // ======== warps 8-15: sign bytes (4096 words, 16 per thread) + index load ========
        const int st = tid - 256;            // 0..255
        if (st < 128)
            sIdx[st] = ((const int4*)mask)[o * INW + st];

        #pragma unroll 4
        for (int j = 0; j < 16; j++) {
            int wlin = j * 256 + st;         // [0, 4096)
            int i    = wlin & 127;           // input index (consecutive across threads: coalesced)
            int b0   = (wlin >> 7) * 4;      // batch group of 4
            unsigned pack = 0;
            #pragma unroll
            for (int k = 0; k < 4; k++) {
                float v   = x[(b0 + k) * INW + i];
                bool  s0  = (v >= 0.0f);
                float thr = s0 ? a0 : -a0;
                bool  s1  = (v >= thr);
                unsigned byte = (s0 ? 1u : 0u) | (s1 ? 16u : 0u);
                pack |= byte << (k * 8);
            }
            *(unsigned*)&sSB[i * 132 + b0] = pack;   // bank = i%32 : conflict-free
        }
    }
    __syncthreads();

    // ---------------- main loop: warp w -> i in [w*8, w*8+8), lane -> batches 4*lane..+3 ----
    float acc0 = 0.0f, acc1 = 0.0f, acc2 = 0.0f, acc3 = 0.0f;
    const unsigned boff = lane * 4u;

    #pragma unroll
    for (int k = 0; k < 8; k++) {
        const int i = w * 8 + k;
        const int4 id = sIdx[i];                         // uniform: broadcast LDS.128
        const float tbl = sW[i * 33 + lane];             // bank (i+lane)%32: conflict-free

        unsigned v0 = *(const unsigned*)&sSB[id.x * 132 + boff];  // banks = lane: conflict-free
        unsigned v1 = *(const unsigned*)&sSB[id.y * 132 + boff];
        unsigned v2 = *(const unsigned*)&sSB[id.z * 132 + boff];
        unsigned v3 = *(const unsigned*)&sSB[id.w * 132 + boff];

        // byte m of VC = (g0 | g1<<4) for batch 4*lane+m
        unsigned VC = (v0 & 0x11111111u)
                    + ((v1 & 0x11111111u) << 1)
                    + ((v2 & 0x11111111u) << 2)
                    + ((v3 & 0x11111111u) << 3);

        unsigned c0 = VC & 0xffu;
        unsigned c1 = (VC >> 8) & 0xffu;
        unsigned c2 = (VC >> 16) & 0xffu;
        unsigned c3 = VC >> 24;

        acc0 += __shfl_sync(0xffffffffu, tbl, c0 & 15u)
              + __shfl_sync(0xffffffffu, tbl, (c0 >> 4) + 16u);
        acc1 += __shfl_sync(0xffffffffu, tbl, c1 & 15u)
              + __shfl_sync(0xffffffffu, tbl, (c1 >> 4) + 16u);
        acc2 += __shfl_sync(0xffffffffu, tbl, c2 & 15u)
              + __shfl_sync(0xffffffffu, tbl, (c2 >> 4) + 16u);
        acc3 += __shfl_sync(0xffffffffu, tbl, c3 & 15u)
              + __shfl_sync(0xffffffffu, tbl, (c3 >> 4) + 16u);
    }

    // partials: red[w][b]
    ((float4*)red)[w * 32 + lane] = make_float4(acc0, acc1, acc2, acc3);
    __syncthreads();

    // ---------------- final reduce over 16 warps, add bias, store ----------------
    if (tid < 128) {
        const int b = tid;
        float tot = bias[o];
        #pragma unroll
        for (int ww = 0; ww < 16; ww++) tot += red[ww * BATCHN + b];  // bank b%32: conflict-free
        out[b * OUTW + o] = tot;
    }
}

// ---------------------------------------------------------------------------
extern "C" void kernel_launch(void* const* d_in, const int* in_sizes, int n_in,
                              void* d_out, int out_size) {
    const float* x      = (const float*)d_in[0];
    const float* weight = (const float*)d_in[1];
    const float* bias   = (const float*)d_in[2];
    const float* means  = (const float*)d_in[3];
    const int*   mask   = (const int*)  d_in[4];
    float* out = (float*)d_out;

    fused_kernel<<<OUTW, 512>>>(x, weight, bias, means, mask, out);
}